// round 14
// baseline (speedup 1.0000x reference)
#include <cuda_runtime.h>
#include <math.h>
#include <stdint.h>

#define BATCH    512
#define MSIZE    4096
#define DDIM     64
#define CDIM     256
#define EPSF     1e-8f
#define NTHREADS 256

#define NSTAGES     4
#define CHUNK_ROWS  64
#define CHUNK_FLTS  (CHUNK_ROWS * DDIM)          // 4096 floats
#define CHUNK_BYTES (CHUNK_FLTS * 4)             // 16384 B
#define NCHUNKS     (MSIZE / CHUNK_ROWS)         // 64

struct Params { float z0, z1, z2, gate, gamma; };

struct __align__(128) Smem {
    float stage[NSTAGES][CHUNK_FLTS];   // 64 KB ring
    float sim0[MSIZE];                  // 16 KB
    float sim1[MSIZE];                  // 16 KB
    float cs[CDIM];
    float q[2][DDIM];
    Params par[2];
    float red8[8];
    float redA[4];
    float redF[8];
    unsigned long long mbar[NSTAGES];
};

// ---------------- PTX helpers ----------------
__device__ __forceinline__ uint32_t smem_u32(const void* p) {
    return (uint32_t)__cvta_generic_to_shared(p);
}
__device__ __forceinline__ void mbar_init(uint32_t mbar, uint32_t count) {
    asm volatile("mbarrier.init.shared.b64 [%0], %1;" :: "r"(mbar), "r"(count) : "memory");
}
__device__ __forceinline__ void mbar_expect_tx(uint32_t mbar, uint32_t tx) {
    asm volatile("mbarrier.arrive.expect_tx.shared.b64 _, [%0], %1;" :: "r"(mbar), "r"(tx) : "memory");
}
__device__ __forceinline__ void mbar_wait(uint32_t mbar, uint32_t parity) {
    asm volatile(
        "{\n\t"
        ".reg .pred P;\n\t"
        "WAIT_LOOP_%=:\n\t"
        "mbarrier.try_wait.parity.acquire.cta.shared::cta.b64 P, [%0], %1, 0x989680;\n\t"
        "@P bra.uni WAIT_DONE_%=;\n\t"
        "bra.uni WAIT_LOOP_%=;\n\t"
        "WAIT_DONE_%=:\n\t"
        "}"
        :: "r"(mbar), "r"(parity) : "memory");
}
__device__ __forceinline__ void bulk_g2s(uint32_t dst, const void* src, uint32_t bytes, uint32_t mbar) {
    asm volatile(
        "cp.async.bulk.shared::cluster.global.mbarrier::complete_tx::bytes [%0], [%1], %2, [%3];"
        :: "r"(dst), "l"(src), "r"(bytes), "r"(mbar) : "memory");
}
__device__ __forceinline__ void named_bar(int id, int count) {
    asm volatile("bar.sync %0, %1;" :: "r"(id), "r"(count) : "memory");
}

// ---------------- reductions ----------------
__device__ __forceinline__ float block_reduce_sum(float v, float* sbuf, int t) {
    #pragma unroll
    for (int o = 16; o > 0; o >>= 1) v += __shfl_xor_sync(0xffffffffu, v, o);
    if ((t & 31) == 0) sbuf[t >> 5] = v;
    __syncthreads();
    float r = 0.0f;
    #pragma unroll
    for (int i = 0; i < 8; i++) r += sbuf[i];
    __syncthreads();
    return r;
}

template<int GSIZE>
__device__ __forceinline__ float group_reduce_sum(float v, float* sbuf, int gt, int barid) {
    #pragma unroll
    for (int o = 16; o > 0; o >>= 1) v += __shfl_xor_sync(0xffffffffu, v, o);
    if ((gt & 31) == 0) sbuf[gt >> 5] = v;
    named_bar(barid, GSIZE);
    float r = 0.0f;
    #pragma unroll
    for (int i = 0; i < GSIZE / 32; i++) r += sbuf[i];
    named_bar(barid, GSIZE);
    return r;
}

__device__ __forceinline__ float softplusf(float x) {
    return (x > 20.0f) ? x : log1pf(expf(x));
}
__device__ __forceinline__ float dot4(float4 a, float4 b) {
    return a.x*b.x + a.y*b.y + a.z*b.z + a.w*b.w;
}

// ---------------- streaming via bulk-async ring ----------------
// NW warps consume; group thread 0 is the producer issuing chunk copies.
// gt in [0, NW*32). barid distinct per concurrent group.
template<int NW>
__device__ void stream_tma(const float* __restrict__ gmem_batch,
                           Smem* S,
                           const float* __restrict__ s_qv,
                           float* __restrict__ sim,
                           int gt, int barid)
{
    const int lane = gt & 31;
    const int wl   = gt >> 5;
    const int sr   = (lane >> 3) & 3;
    const int h    = lane & 7;
    const bool elected = (gt == 0);

    const float4* q4 = (const float4*)s_qv;
    const float4 bqa = q4[h];
    const float4 bqb = q4[h + 8];

    uint32_t mbar_u32[NSTAGES], stage_u32[NSTAGES];
    #pragma unroll
    for (int s = 0; s < NSTAGES; s++) {
        mbar_u32[s]  = smem_u32(&S->mbar[s]);
        stage_u32[s] = smem_u32(&S->stage[s][0]);
    }

    if (elected) {
        #pragma unroll
        for (int s = 0; s < NSTAGES; s++) {
            mbar_expect_tx(mbar_u32[s], CHUNK_BYTES);
            bulk_g2s(stage_u32[s], gmem_batch + (size_t)s * CHUNK_FLTS,
                     CHUNK_BYTES, mbar_u32[s]);
        }
    }

    constexpr int KITER = CHUNK_ROWS / (NW * 4);

    #pragma unroll 1
    for (int c = 0; c < NCHUNKS; c++) {
        const int s  = c & (NSTAGES - 1);
        const int ph = (c >> 2) & 1;
        mbar_wait(mbar_u32[s], ph);

        const float4* st4 = (const float4*)&S->stage[s][0];
        #pragma unroll
        for (int k = 0; k < KITER; k++) {
            const int lr = k * NW * 4 + wl * 4 + sr;      // local row in chunk
            float4 a = st4[lr * 16 + h];
            float4 b = st4[lr * 16 + 8 + h];
            float d = dot4(a, bqa) + dot4(b, bqb);
            float n = dot4(a, a)   + dot4(b, b);
            #pragma unroll
            for (int o = 4; o > 0; o >>= 1) {
                d += __shfl_xor_sync(0xffffffffu, d, o);
                n += __shfl_xor_sync(0xffffffffu, n, o);
            }
            if (h == 0) sim[c * CHUNK_ROWS + lr] = d * rsqrtf(n + 1e-16f);
        }

        named_bar(barid, NW * 32);     // all reads of stage s done
        if (elected) {
            const int nc = c + NSTAGES;
            if (nc < NCHUNKS) {
                mbar_expect_tx(mbar_u32[s], CHUNK_BYTES);
                bulk_g2s(stage_u32[s], gmem_batch + (size_t)nc * CHUNK_FLTS,
                         CHUNK_BYTES, mbar_u32[s]);
            }
        }
    }
}

// ---------------- epilogue (unchanged from R12 winner) ----------------
template<int GSIZE>
__device__ void epilogue(float* __restrict__ s_sim,
                         const float* __restrict__ prow,
                         float* __restrict__ orow,
                         const Params P, float* redbuf, int gt, int barid)
{
    constexpr int K = MSIZE / GSIZE;

    float ls = 0.0f;
    #pragma unroll
    for (int k = 0; k < K; k++) {
        int j = gt + k * GSIZE;
        float e = __expf(s_sim[j]);
        s_sim[j] = e;
        ls += e;
    }
    const float Z = group_reduce_sum<GSIZE>(ls, redbuf, gt, barid);

    const float invZg = P.gate / Z;
    const float og    = 1.0f - P.gate;
    #pragma unroll
    for (int k = 0; k < K; k++) {
        int j = gt + k * GSIZE;
        s_sim[j] = s_sim[j] * invZg + og * __ldcs(&prow[j]);
    }
    named_bar(barid, GSIZE);

    float p[K];
    float lp = 0.0f;
    #pragma unroll
    for (int k = 0; k < K; k++) {
        int j = gt + k * GSIZE;
        float sh = s_sim[(j - 1) & (MSIZE - 1)] * P.z0
                 + s_sim[j]                     * P.z1
                 + s_sim[(j + 1) & (MSIZE - 1)] * P.z2;
        p[k] = __powf(sh + EPSF, P.gamma);
        lp += p[k];
    }
    const float Psum = group_reduce_sum<GSIZE>(lp, redbuf, gt, barid);

    const float inv = 1.0f / (Psum + EPSF);
    #pragma unroll
    for (int k = 0; k < K; k++) {
        int j = gt + k * GSIZE;
        __stcs(&orow[j], p[k] * inv);
    }
}

extern __shared__ __align__(128) unsigned char smem_raw[];

__global__ __launch_bounds__(NTHREADS, 2)
void ntm_head_kernel(const float* __restrict__ memory,
                     const float* __restrict__ cs_all,
                     const float* __restrict__ prev,
                     const float* __restrict__ Wk,
                     const float* __restrict__ Wb,    const float* __restrict__ bb,
                     const float* __restrict__ Wgate, const float* __restrict__ bgate,
                     const float* __restrict__ Ws,    const float* __restrict__ bs,
                     const float* __restrict__ Wg,    const float* __restrict__ bg,
                     float* __restrict__ out)
{
    Smem* S = reinterpret_cast<Smem*>(smem_raw);

    const int t    = threadIdx.x;
    const int b0   = blockIdx.x * 2;

    // mbarrier init (completion counted purely via expect_tx transactions)
    if (t == 0) {
        #pragma unroll
        for (int s = 0; s < NSTAGES; s++) mbar_init(smem_u32(&S->mbar[s]), 1);
    }
    __syncthreads();

    // =========== Prologue for both batches (all 256 threads) ==========
    for (int s = 0; s < 2; s++) {
        const int b = b0 + s;
        S->cs[t] = cs_all[(size_t)b * CDIM + t];
        __syncthreads();

        const float csv = S->cs[t];
        float zb    = block_reduce_sum(csv * Wb[t],         S->red8, t);
        float zgate = block_reduce_sum(csv * Wgate[t],      S->red8, t);
        float zG    = block_reduce_sum(csv * Wg[t],         S->red8, t);
        float z0    = block_reduce_sum(csv * Ws[t * 3 + 0], S->red8, t);
        float z1    = block_reduce_sum(csv * Ws[t * 3 + 1], S->red8, t);
        float z2    = block_reduce_sum(csv * Ws[t * 3 + 2], S->red8, t);

        const float beta  = softplusf(zb + bb[0]) + 1.0f;
        const float gate  = 1.0f / (1.0f + __expf(-(zgate + bgate[0])));
        const float gamma = softplusf(zG + bg[0]) + 1.0f;
        z0 += bs[0]; z1 += bs[1]; z2 += bs[2];
        {
            float zm = fmaxf(z0, fmaxf(z1, z2));
            z0 = __expf(z0 - zm); z1 = __expf(z1 - zm); z2 = __expf(z2 - zm);
            float iz = 1.0f / (z0 + z1 + z2);
            z0 *= iz; z1 *= iz; z2 *= iz;
        }

        if (t < DDIM) {
            float acc = 0.0f;
            #pragma unroll 8
            for (int c = 0; c < CDIM; c++) acc = fmaf(S->cs[c], Wk[c * DDIM + t], acc);
            S->q[s][t] = acc;
        }
        float lq = (t < DDIM) ? S->q[s][t] * S->q[s][t] : 0.0f;
        float qn2 = block_reduce_sum(lq, S->red8, t);
        const float qscale = beta / (sqrtf(qn2) + EPSF);
        if (t < DDIM) S->q[s][t] *= qscale;

        if (t == 0) {
            S->par[s].z0 = z0; S->par[s].z1 = z1; S->par[s].z2 = z2;
            S->par[s].gate = gate; S->par[s].gamma = gamma;
        }
        __syncthreads();
    }

    const float* mem0 = memory + (size_t)b0 * MSIZE * DDIM;
    const float* mem1 = mem0 + (size_t)MSIZE * DDIM;

    // =========== Stage 0: stream b0 with all 8 warps ==================
    stream_tma<8>(mem0, S, S->q[0], S->sim0, t, 3);
    __syncthreads();   // ring fully consumed; parity back to 0

    // =========== Stage 1: epilogue(b0) warps 0-3 | stream b1 warps 4-7
    if (t < 128) {
        Params P0 = S->par[0];
        epilogue<128>(S->sim0, prev + (size_t)b0 * MSIZE,
                      out + (size_t)b0 * MSIZE, P0, S->redA, t, 1);
    } else {
        stream_tma<4>(mem1, S, S->q[1], S->sim1, t - 128, 2);
    }
    __syncthreads();

    // =========== Stage 2: epilogue(b1) on all 8 warps =================
    {
        Params P1 = S->par[1];
        epilogue<256>(S->sim1, prev + (size_t)(b0 + 1) * MSIZE,
                      out + (size_t)(b0 + 1) * MSIZE, P1, S->redF, t, 0);
    }
}

extern "C" void kernel_launch(void* const* d_in, const int* in_sizes, int n_in,
                              void* d_out, int out_size) {
    const float* memory = (const float*)d_in[0];
    const float* cs     = (const float*)d_in[1];
    const float* prev   = (const float*)d_in[2];
    const float* Wk     = (const float*)d_in[3];
    const float* Wb     = (const float*)d_in[4];
    const float* bb     = (const float*)d_in[5];
    const float* Wgate  = (const float*)d_in[6];
    const float* bgate  = (const float*)d_in[7];
    const float* Ws     = (const float*)d_in[8];
    const float* bs     = (const float*)d_in[9];
    const float* Wg     = (const float*)d_in[10];
    const float* bg     = (const float*)d_in[11];
    float* out = (float*)d_out;

    static int configured = 0;
    if (!configured) {
        cudaFuncSetAttribute(ntm_head_kernel,
                             cudaFuncAttributeMaxDynamicSharedMemorySize,
                             (int)sizeof(Smem));
        configured = 1;
    }

    ntm_head_kernel<<<BATCH / 2, NTHREADS, sizeof(Smem)>>>(
        memory, cs, prev, Wk, Wb, bb, Wgate, bgate, Ws, bs, Wg, bg, out);
}

// round 16
// speedup vs baseline: 1.2181x; 1.2181x over previous
#include <cuda_runtime.h>
#include <math.h>

#define BATCH    512
#define MSIZE    4096
#define DDIM     64
#define CDIM     256
#define EPSF     1e-8f
#define NTHREADS 256

struct Params { float z0, z1, z2, gate, gamma; };

__device__ __forceinline__ void named_bar(int id, int count) {
    asm volatile("bar.sync %0, %1;" :: "r"(id), "r"(count) : "memory");
}

// Full-block (256-thread) reduce for the prologue.
__device__ __forceinline__ float block_reduce_sum(float v, float* sbuf, int t) {
    #pragma unroll
    for (int o = 16; o > 0; o >>= 1) v += __shfl_xor_sync(0xffffffffu, v, o);
    if ((t & 31) == 0) sbuf[t >> 5] = v;
    __syncthreads();
    float r = 0.0f;
    #pragma unroll
    for (int i = 0; i < 8; i++) r += sbuf[i];
    __syncthreads();
    return r;
}

// Group reduce over GSIZE threads using named barrier `barid`.
template<int GSIZE>
__device__ __forceinline__ float group_reduce_sum(float v, float* sbuf, int gt, int barid) {
    #pragma unroll
    for (int o = 16; o > 0; o >>= 1) v += __shfl_xor_sync(0xffffffffu, v, o);
    if ((gt & 31) == 0) sbuf[gt >> 5] = v;
    named_bar(barid, GSIZE);
    float r = 0.0f;
    #pragma unroll
    for (int i = 0; i < GSIZE / 32; i++) r += sbuf[i];
    named_bar(barid, GSIZE);
    return r;
}

__device__ __forceinline__ float softplusf(float x) {
    return (x > 20.0f) ? x : log1pf(expf(x));
}

__device__ __forceinline__ float dot4(float4 a, float4 b) {
    return a.x*b.x + a.y*b.y + a.z*b.z + a.w*b.w;
}

// Stream for one batch with NW warps: 8 lanes/row, 8 rows per warp per
// iteration (16 independent LDG.128 = 2KB in flight per warp). Fuses the
// softmax exp at production time: stores e = expf(beta*cos) into sim[] and
// accumulates the per-warp partial normalizer into zslots[wl].
template<int NW>
__device__ void stream_sim(const float4* __restrict__ memrow,  // batch base (float4 units)
                           const float* __restrict__ s_qv,     // beta-folded query
                           float* __restrict__ sim,
                           float* __restrict__ zslots,
                           int wl, int lane)
{
    const int sr = (lane >> 3) & 3;
    const int h  = lane & 7;
    const int rb = wl * 4 + sr;
    constexpr int SP   = NW * 4;    // spacing between row-quads
    constexpr int STEP = NW * 32;   // rows covered per iteration (8 quads)

    const float4* q4 = (const float4*)s_qv;
    const float4 bqa = q4[h];
    const float4 bqb = q4[h + 8];
    const float4* mem4 = memrow + h;

    float4 buf[16];
    float d[8], n[8];
    float zacc = 0.0f;

    #pragma unroll 1
    for (int it = 0; it < MSIZE; it += STEP) {
        const int r0 = it + rb;

        #pragma unroll
        for (int q = 0; q < 8; q++) {
            const float4* p = mem4 + (size_t)(r0 + q * SP) * 16;
            buf[2 * q]     = __ldcs(p);
            buf[2 * q + 1] = __ldcs(p + 8);
        }

        #pragma unroll
        for (int q = 0; q < 8; q++) {
            float4 a = buf[2 * q], c = buf[2 * q + 1];
            d[q] = dot4(a, bqa) + dot4(c, bqb);
            n[q] = dot4(a, a)   + dot4(c, c);
        }

        #pragma unroll
        for (int o = 4; o > 0; o >>= 1) {
            #pragma unroll
            for (int q = 0; q < 8; q++) {
                d[q] += __shfl_xor_sync(0xffffffffu, d[q], o);
                n[q] += __shfl_xor_sync(0xffffffffu, n[q], o);
            }
        }
        if (h == 0) {
            #pragma unroll
            for (int q = 0; q < 8; q++) {
                float e = __expf(d[q] * rsqrtf(n[q] + 1e-16f));
                sim[r0 + q * SP] = e;
                zacc += e;
            }
        }
    }

    // zacc nonzero only on lanes 0/8/16/24; full-warp reduce then store.
    #pragma unroll
    for (int o = 16; o > 0; o >>= 1) zacc += __shfl_xor_sync(0xffffffffu, zacc, o);
    if (lane == 0) zslots[wl] = zacc;
}

// Epilogue: Z from precomputed partials -> gate blend (in place) ->
// circular conv + pow (p staged in registers) -> normalize -> store.
template<int GSIZE, int NSLOT>
__device__ void epilogue(float* __restrict__ s_sim,
                         const float* __restrict__ zslots,
                         const float* __restrict__ prow,
                         float* __restrict__ orow,
                         const Params P, float* redbuf, int gt, int barid)
{
    constexpr int K = MSIZE / GSIZE;

    float Z = 0.0f;
    #pragma unroll
    for (int i = 0; i < NSLOT; i++) Z += zslots[i];

    const float invZg = P.gate / Z;
    const float og    = 1.0f - P.gate;
    #pragma unroll
    for (int k = 0; k < K; k++) {
        int j = gt + k * GSIZE;
        s_sim[j] = s_sim[j] * invZg + og * __ldcs(&prow[j]);   // g in place
    }
    named_bar(barid, GSIZE);   // all g visible before neighbor reads

    float p[K];
    float lp = 0.0f;
    #pragma unroll
    for (int k = 0; k < K; k++) {
        int j = gt + k * GSIZE;
        float sh = s_sim[(j - 1) & (MSIZE - 1)] * P.z0
                 + s_sim[j]                     * P.z1
                 + s_sim[(j + 1) & (MSIZE - 1)] * P.z2;
        p[k] = __powf(sh + EPSF, P.gamma);
        lp += p[k];
    }
    const float Psum = group_reduce_sum<GSIZE>(lp, redbuf, gt, barid);

    const float inv = 1.0f / (Psum + EPSF);
    #pragma unroll
    for (int k = 0; k < K; k++) {
        int j = gt + k * GSIZE;
        __stcs(&orow[j], p[k] * inv);
    }
}

__global__ __launch_bounds__(NTHREADS, 2)
void ntm_head_kernel(const float* __restrict__ memory,
                     const float* __restrict__ cs_all,
                     const float* __restrict__ prev,
                     const float* __restrict__ Wk,
                     const float* __restrict__ Wb,    const float* __restrict__ bb,
                     const float* __restrict__ Wgate, const float* __restrict__ bgate,
                     const float* __restrict__ Ws,    const float* __restrict__ bs,
                     const float* __restrict__ Wg,    const float* __restrict__ bg,
                     float* __restrict__ out)
{
    __shared__ float s_sim0[MSIZE];
    __shared__ float s_sim1[MSIZE];
    __shared__ float s_cs[CDIM];
    __shared__ __align__(16) float s_q[2][DDIM];
    __shared__ Params s_par[2];
    __shared__ float s_red8[8];    // prologue reduces (256 threads)
    __shared__ float s_redA[4];    // group-A epilogue reduces (128 threads)
    __shared__ float s_redF[8];    // final epilogue reduces (256 threads)
    __shared__ float s_zp0[8];     // softmax partials, batch 0 (8 warps)
    __shared__ float s_zp1[4];     // softmax partials, batch 1 (4 warps)

    const int t    = threadIdx.x;
    const int wid  = t >> 5;
    const int lane = t & 31;
    const int b0   = blockIdx.x * 2;

    // =========== Prologue for both batches (all 256 threads) ==========
    for (int s = 0; s < 2; s++) {
        const int b = b0 + s;
        s_cs[t] = cs_all[(size_t)b * CDIM + t];
        __syncthreads();

        const float csv = s_cs[t];
        float zb    = block_reduce_sum(csv * Wb[t],         s_red8, t);
        float zgate = block_reduce_sum(csv * Wgate[t],      s_red8, t);
        float zG    = block_reduce_sum(csv * Wg[t],         s_red8, t);
        float z0    = block_reduce_sum(csv * Ws[t * 3 + 0], s_red8, t);
        float z1    = block_reduce_sum(csv * Ws[t * 3 + 1], s_red8, t);
        float z2    = block_reduce_sum(csv * Ws[t * 3 + 2], s_red8, t);

        const float beta  = softplusf(zb + bb[0]) + 1.0f;
        const float gate  = 1.0f / (1.0f + __expf(-(zgate + bgate[0])));
        const float gamma = softplusf(zG + bg[0]) + 1.0f;
        z0 += bs[0]; z1 += bs[1]; z2 += bs[2];
        {
            float zm = fmaxf(z0, fmaxf(z1, z2));
            z0 = __expf(z0 - zm); z1 = __expf(z1 - zm); z2 = __expf(z2 - zm);
            float iz = 1.0f / (z0 + z1 + z2);
            z0 *= iz; z1 *= iz; z2 *= iz;
        }

        if (t < DDIM) {
            float acc = 0.0f;
            #pragma unroll 8
            for (int c = 0; c < CDIM; c++) acc = fmaf(s_cs[c], Wk[c * DDIM + t], acc);
            s_q[s][t] = acc;
        }
        float lq = (t < DDIM) ? s_q[s][t] * s_q[s][t] : 0.0f;
        float qn2 = block_reduce_sum(lq, s_red8, t);
        const float qscale = beta / (sqrtf(qn2) + EPSF);
        if (t < DDIM) s_q[s][t] *= qscale;

        if (t == 0) {
            s_par[s].z0 = z0; s_par[s].z1 = z1; s_par[s].z2 = z2;
            s_par[s].gate = gate; s_par[s].gamma = gamma;
        }
        __syncthreads();   // protect s_cs reuse + publish s_par/s_q
    }

    const float4* mem0 = (const float4*)memory + (size_t)b0 * MSIZE * 16;
    const float4* mem1 = mem0 + (size_t)MSIZE * 16;

    // =========== Stage 0: stream b0 with all 8 warps ==================
    stream_sim<8>(mem0, s_q[0], s_sim0, s_zp0, wid, lane);
    __syncthreads();

    // =========== Stage 1: epilogue(b0) warps 0-3 | stream b1 warps 4-7
    if (t < 128) {
        Params P0 = s_par[0];
        epilogue<128, 8>(s_sim0, s_zp0, prev + (size_t)b0 * MSIZE,
                         out + (size_t)b0 * MSIZE, P0, s_redA, t, 1);
    } else {
        stream_sim<4>(mem1, s_q[1], s_sim1, s_zp1, wid - 4, lane);
    }
    __syncthreads();

    // =========== Stage 2: epilogue(b1) on all 8 warps =================
    {
        Params P1 = s_par[1];
        epilogue<256, 4>(s_sim1, s_zp1, prev + (size_t)(b0 + 1) * MSIZE,
                         out + (size_t)(b0 + 1) * MSIZE, P1, s_redF, t, 0);
    }
}

extern "C" void kernel_launch(void* const* d_in, const int* in_sizes, int n_in,
                              void* d_out, int out_size) {
    const float* memory = (const float*)d_in[0];
    const float* cs     = (const float*)d_in[1];
    const float* prev   = (const float*)d_in[2];
    const float* Wk     = (const float*)d_in[3];
    const float* Wb     = (const float*)d_in[4];
    const float* bb     = (const float*)d_in[5];
    const float* Wgate  = (const float*)d_in[6];
    const float* bgate  = (const float*)d_in[7];
    const float* Ws     = (const float*)d_in[8];
    const float* bs     = (const float*)d_in[9];
    const float* Wg     = (const float*)d_in[10];
    const float* bg     = (const float*)d_in[11];
    float* out = (float*)d_out;

    ntm_head_kernel<<<BATCH / 2, NTHREADS>>>(memory, cs, prev, Wk, Wb, bb,
                                             Wgate, bgate, Ws, bs, Wg, bg, out);
}